// round 12
// baseline (speedup 1.0000x reference)
#include <cuda_runtime.h>
#include <cstdint>
#include <math.h>

// ---------------- problem constants ----------------
#define BB   64
#define SS   512
#define DIN  64
#define HH   512
#define NLAY 4
#define DOUT 64

// ---------------- config ----------------
#define NB   128         // 32 blocks per layer
#define NT   256         // 8 warps: 2(m) x 2(n) x 2(k)
#define BPL  32
#define UPB  16          // hidden units per block (64 gate rows)
#define KC   128         // K elements per chunk

// smem layout (phase 1), bytes
#define ROWB      272                 // bytes per operand row (256 data + 16 pad)
#define PLANE_B   17408               // 64 * 272
#define BUF_B     69632               // 4 planes: Ahi, Alo, Bhi, Blo
#define DS_OFF_F  34816               // float idx of Ds partials (= buf2 start)
#define DSPLANE_F 4352                // 64 * 68 floats per wk plane
#define DPITCH    68
#define PAD       68
#define SMEM_BYTES 208896             // 3 bufs; >= phase-2 need (156928)

// ---------------- persistent device state ----------------
__device__ unsigned short g_Whi[NLAY][2048][1024];    // pre-split weights, block-row order
__device__ unsigned short g_Wlo[NLAY][2048][1024];    // unwritten k stays 0
__device__ unsigned short g_acthi[NLAY][2][BB][1024]; // per-layer B operand planes
__device__ unsigned short g_actlo[NLAY][2][BB][1024];
__device__ unsigned short g_xhi[SS][BB][DIN];         // pre-split input
__device__ unsigned short g_xlo[SS][BB][DIN];
__device__ float g_h3[(size_t)BB * SS * HH];          // layer-3 h for phase 2
__device__ int g_cnt[NLAY];                           // per-layer full progress
__device__ int g_cg[NLAY][4];                         // per-layer per-128-unit-group progress
__device__ unsigned int g_arrive = 0;
__device__ unsigned int g_gen    = 0;

// ---------------- helpers ----------------
__device__ __forceinline__ uint32_t smem_u32(const void* p) {
    uint32_t a;
    asm("{ .reg .u64 t; cvta.to.shared.u64 t, %1; cvt.u32.u64 %0, t; }" : "=r"(a) : "l"(p));
    return a;
}
__device__ __forceinline__ unsigned short bf16rn(float v) {
    uint32_t u = __float_as_uint(v);
    uint32_t r = u + 0x7FFFu + ((u >> 16) & 1u);
    return (unsigned short)(r >> 16);
}
__device__ __forceinline__ void split2(float v, unsigned short& h, unsigned short& l) {
    h = bf16rn(v);
    float hf = __uint_as_float((uint32_t)h << 16);
    l = bf16rn(v - hf);
}
__device__ __forceinline__ float fsig(float x)   { return __fdividef(1.0f, 1.0f + __expf(-x)); }
__device__ __forceinline__ float ftanh_(float x) { return __fdividef(2.0f, 1.0f + __expf(-2.0f * x)) - 1.0f; }

__device__ __forceinline__ void poll_ge(int* p, int v) {
    int x;
    while (true) {
        asm volatile("ld.global.acquire.gpu.b32 %0, [%1];" : "=r"(x) : "l"(p) : "memory");
        if (x >= v) return;
        __nanosleep(32);
    }
}

__device__ __forceinline__ void mma_bf16(float* c, const uint32_t* a, const uint32_t* b) {
    asm volatile(
        "mma.sync.aligned.m16n8k16.row.col.f32.bf16.bf16.f32 "
        "{%0,%1,%2,%3}, {%4,%5,%6,%7}, {%8,%9}, {%0,%1,%2,%3};"
        : "+f"(c[0]), "+f"(c[1]), "+f"(c[2]), "+f"(c[3])
        : "r"(a[0]), "r"(a[1]), "r"(a[2]), "r"(a[3]), "r"(b[0]), "r"(b[1]));
}
__device__ __forceinline__ void ldsm4(uint32_t* r, uint32_t saddr) {
    asm volatile("ldmatrix.sync.aligned.m8n8.x4.shared.b16 {%0,%1,%2,%3}, [%4];"
                 : "=r"(r[0]), "=r"(r[1]), "=r"(r[2]), "=r"(r[3]) : "r"(saddr));
}
__device__ __forceinline__ void cp16(uint32_t d, const void* s) {
    asm volatile("cp.async.cg.shared.global [%0], [%1], 16;" :: "r"(d), "l"(s) : "memory");
}
#define CPC()  asm volatile("cp.async.commit_group;" ::: "memory")
#define CPW1() asm volatile("cp.async.wait_group 1;" ::: "memory")
#define CPW0() asm volatile("cp.async.wait_group 0;" ::: "memory")

__device__ __forceinline__ void gridbar(unsigned int& lgen) {
    __syncthreads();
    __threadfence();
    if (threadIdx.x == 0) {
        unsigned int old = atomicAdd(&g_arrive, 1u);
        if (((old + 1u) % NB) == 0u) {
            atomicAdd(&g_gen, 1u);
        } else {
            while (*((volatile unsigned int*)&g_gen) < lgen + 1u) { __nanosleep(32); }
        }
    }
    lgen += 1u;
    __syncthreads();
    __threadfence();
}

// ---- staging pieces (NT=256: j<4 covers a full 64x256B plane pair) ----
__device__ __forceinline__ void stageA(uint32_t smb, int buf, int ch, int layer, int blk) {
    const int tid = threadIdx.x;
    const uint32_t base = smb + (uint32_t)buf * BUF_B;
    #pragma unroll
    for (int j = 0; j < 4; ++j) {
        const int idx = tid + 256 * j, row = idx >> 4, q = idx & 15;
        const uint32_t d = base + (uint32_t)(row * ROWB + q * 16);
        const int k = ch * KC + q * 8;
        cp16(d,           &g_Whi[layer][blk * 64 + row][k]);
        cp16(d + PLANE_B, &g_Wlo[layer][blk * 64 + row][k]);
    }
}
__device__ __forceinline__ void stageB(uint32_t smb, int buf, int ch, int layer,
                                       int t, int Kin) {
    const int tid = threadIdx.x;
    const uint32_t base = smb + (uint32_t)buf * BUF_B;
    #pragma unroll
    for (int j = 0; j < 4; ++j) {
        const int idx = tid + 256 * j, n = idx >> 4, q = idx & 15;
        const uint32_t d = base + 2u * PLANE_B + (uint32_t)(n * ROWB + q * 16);
        const int k = ch * KC + q * 8;
        const unsigned short *sh, *sl;
        if (layer == 0 && k < DIN) {
            sh = &g_xhi[t][n][k];
            sl = &g_xlo[t][n][k];
        } else {
            const int slot = (k < Kin) ? (t & 1) : ((t & 1) ^ 1);
            sh = &g_acthi[layer][slot][n][k];
            sl = &g_actlo[layer][slot][n][k];
        }
        cp16(d, sh);
        cp16(d + PLANE_B, sl);
    }
}

__global__ void __launch_bounds__(NT, 1) lstm_mma_kernel(
    const float* __restrict__ x,
    const float* __restrict__ W0, const float* __restrict__ b0,
    const float* __restrict__ W1, const float* __restrict__ b1,
    const float* __restrict__ W2, const float* __restrict__ b2,
    const float* __restrict__ W3, const float* __restrict__ b3,
    const float* __restrict__ lng, const float* __restrict__ lnb,
    const float* __restrict__ Wo,  const float* __restrict__ bo,
    float* __restrict__ out)
{
    extern __shared__ char smc[];
    float* smf = (float*)smc;
    const int tid = threadIdx.x;
    const int bx  = blockIdx.x;
    unsigned int lgen = *((volatile unsigned int*)&g_gen);
    const uint32_t smb = smem_u32(smc);

    const float* Wsrc[4] = {W0, W1, W2, W3};
    const float* bsrc[4] = {b0, b1, b2, b3};

    // ---------------- phase 0: reset, zero act planes, split W and x ----------
    if (bx == 0 && tid < 4)  g_cnt[tid] = 0;
    if (bx == 0 && tid < 16) ((int*)g_cg)[tid] = 0;
    {
        uint4 z = make_uint4(0, 0, 0, 0);
        uint4* ph = (uint4*)&g_acthi[0][0][0][0];
        uint4* pl = (uint4*)&g_actlo[0][0][0][0];
        const int n16 = NLAY * 2 * BB * 1024 * 2 / 16;
        for (int i = bx * NT + tid; i < n16; i += NB * NT) { ph[i] = z; pl[i] = z; }
    }
    {
        for (int rr = 0; rr < 64; ++rr) {
            const int gr = bx * 64 + rr;
            const int l = gr >> 11, r = gr & 2047;
            const int blk2 = r >> 6, rloc = r & 63, iu = rloc >> 2, g = rloc & 3;
            const int fanin = (l == 0) ? (DIN + HH) : (2 * HH);
            const float* src = Wsrc[l] + (size_t)(g * HH + blk2 * UPB + iu) * fanin;
            const int k = tid * 4;
            if (k < fanin) {
                float4 v = __ldg((const float4*)(src + k));
                unsigned short h0, l0, h1, l1, h2, l2, h3, l3;
                split2(v.x, h0, l0); split2(v.y, h1, l1);
                split2(v.z, h2, l2); split2(v.w, h3, l3);
                // layer 0: own-h columns relocated by +64 (pad [64,128) stays zero)
                const int kk = (l == 0 && k >= DIN) ? k + 64 : k;
                *(uint2*)&g_Whi[l][r][kk] =
                    make_uint2((uint32_t)h0 | ((uint32_t)h1 << 16), (uint32_t)h2 | ((uint32_t)h3 << 16));
                *(uint2*)&g_Wlo[l][r][kk] =
                    make_uint2((uint32_t)l0 | ((uint32_t)l1 << 16), (uint32_t)l2 | ((uint32_t)l3 << 16));
            }
        }
    }
    {
        for (int i = bx * NT + tid; i < SS * BB * (DIN / 2); i += NB * NT) {
            const int k2 = i & 31, n = (i >> 5) & 63, tt = i >> 11;
            float2 v = __ldg((const float2*)&x[((size_t)n * SS + tt) * DIN + k2 * 2]);
            unsigned short h0, l0, h1, l1;
            split2(v.x, h0, l0); split2(v.y, h1, l1);
            *(uint32_t*)&g_xhi[tt][n][k2 * 2] = (uint32_t)h0 | ((uint32_t)h1 << 16);
            *(uint32_t*)&g_xlo[tt][n][k2 * 2] = (uint32_t)l0 | ((uint32_t)l1 << 16);
        }
    }
    gridbar(lgen);

    // ---------------- phase 1: wavefront LSTM, fine-grained group handshake ---
    const int layer = bx >> 5;
    const int blk   = bx & 31;
    const int u0    = blk * UPB;
    const float* bl = bsrc[layer];
    const int Kin   = (layer == 0) ? DIN : HH;
    const int kst   = (layer == 0) ? 128 : 512;   // own-h store offset
    const int nch   = (layer == 0) ? 5 : 8;

    const int lane = tid & 31, wid = tid >> 5;
    const int wm = wid & 1, wn = (wid >> 1) & 1, wk = wid >> 2;  // 2x2x2

    const uint32_t aoff0 = (uint32_t)((wm * 32 + (lane & 15)) * ROWB + (lane >> 4) * 16);
    const uint32_t aoff1 = aoff0 + 16u * ROWB;
    const uint32_t boff0 = 2u * PLANE_B +
        (uint32_t)((wn * 32 + (lane & 7) + ((lane >> 4) << 3)) * ROWB + (((lane >> 3) & 1) << 4));
    const uint32_t boff1 = boff0 + 16u * ROWB;
    const uint32_t ksb0 = (uint32_t)(wk * 4) * 32u;   // k-half start

    const int eu  = tid >> 4;                   // epilogue unit 0..15
    const int eb0 = (tid & 15) * 4;             // epilogue batch base (4 each)
    const float bzi = __ldg(&bl[0 * HH + u0 + eu]);
    const float bzf = __ldg(&bl[1 * HH + u0 + eu]);
    const float bzg = __ldg(&bl[2 * HH + u0 + eu]);
    const float bzo = __ldg(&bl[3 * HH + u0 + eu]);
    float c_st[4] = {0.f, 0.f, 0.f, 0.f};

    float* Ds = smf + DS_OFF_F;                 // 2 partial planes (per wk) in buf2
    const int mygrp = blk >> 3;                 // this block's 128-unit group

    // initial AA: weight chunks 0,1 for step 0 (one commit group)
    stageA(smb, 0, 0, layer, blk);
    stageA(smb, 1, 1, layer, blk);
    CPC();

    for (int t = 0; t < SS; ++t) {
        // fine-grained data polls for chunks 0,1 (parallel)
        if (layer == 0) {
            if (tid == 0 && t > 0) poll_ge(&g_cg[0][0], 8 * t);   // chunk1 = own grp 0
        } else {
            if (tid == 0) poll_ge(&g_cg[layer - 1][0], 8 * (t + 1));
            if (tid == 1) poll_ge(&g_cg[layer - 1][1], 8 * (t + 1));
        }
        __syncthreads();

        stageB(smb, 0, 0, layer, t, Kin); CPC();
        stageB(smb, 1, 1, layer, t, Kin); CPC();

        float acc[2][4][4];
        #pragma unroll
        for (int mt = 0; mt < 2; ++mt)
            #pragma unroll
            for (int nt = 0; nt < 4; ++nt)
                #pragma unroll
                for (int q = 0; q < 4; ++q) acc[mt][nt][q] = 0.f;

        for (int ch = 0; ch < nch; ++ch) {
            if (ch == nch - 1) { CPW0(); } else { CPW1(); }
            // poll dependency for chunk ch+2 before staging it
            const int cn = ch + 2;
            if (tid == 0 && cn < nch) {
                int need = 0; int* src = 0;
                if (layer == 0) {
                    if (cn >= 1) { src = &g_cg[0][cn - 1]; need = 8 * t; }
                } else if (cn < 4) {
                    src = &g_cg[layer - 1][cn]; need = 8 * (t + 1);
                } else {
                    src = &g_cg[layer][cn - 4]; need = 8 * t;
                }
                if (need > 0) poll_ge(src, need);
            }
            __syncthreads();                    // chunk ch ready; prior buffer free
            if (cn < nch) {
                const int b2 = cn % 3;
                stageA(smb, b2, cn, layer, blk);
                stageB(smb, b2, cn, layer, t, Kin);
                CPC();
            }

            const uint32_t bb = smb + (uint32_t)(ch % 3) * BUF_B;
            #pragma unroll
            for (int ks0 = 0; ks0 < 4; ++ks0) {
                const uint32_t kb = ksb0 + (uint32_t)ks0 * 32u;
                uint32_t ah0[4], ah1[4], al0[4], al1[4];
                uint32_t bh0[4], bh1[4], bl0[4], bl1[4];
                ldsm4(ah0, bb + aoff0 + kb);
                ldsm4(ah1, bb + aoff1 + kb);
                ldsm4(al0, bb + aoff0 + PLANE_B + kb);
                ldsm4(al1, bb + aoff1 + PLANE_B + kb);
                ldsm4(bh0, bb + boff0 + kb);
                ldsm4(bh1, bb + boff1 + kb);
                ldsm4(bl0, bb + boff0 + PLANE_B + kb);
                ldsm4(bl1, bb + boff1 + PLANE_B + kb);
                const uint32_t* bhv[4] = {bh0, bh0 + 2, bh1, bh1 + 2};
                const uint32_t* blv[4] = {bl0, bl0 + 2, bl1, bl1 + 2};
                #pragma unroll
                for (int nt = 0; nt < 4; ++nt) {
                    mma_bf16(acc[0][nt], ah0, bhv[nt]);
                    mma_bf16(acc[0][nt], ah0, blv[nt]);
                    mma_bf16(acc[0][nt], al0, bhv[nt]);
                    mma_bf16(acc[1][nt], ah1, bhv[nt]);
                    mma_bf16(acc[1][nt], ah1, blv[nt]);
                    mma_bf16(acc[1][nt], al1, bhv[nt]);
                }
            }
        }

        // each k-half warp group writes its own partial plane (no RMW)
        {
            float* Dp = Ds + wk * DSPLANE_F;
            const int r = lane >> 2, cp2 = (lane & 3) * 2;
            #pragma unroll
            for (int mt = 0; mt < 2; ++mt)
                #pragma unroll
                for (int nt = 0; nt < 4; ++nt) {
                    const int row = wm * 32 + mt * 16 + r;
                    const int col = wn * 32 + nt * 8 + cp2;
                    *(float2*)&Dp[row * DPITCH + col] =
                        make_float2(acc[mt][nt][0], acc[mt][nt][1]);
                    *(float2*)&Dp[(row + 8) * DPITCH + col] =
                        make_float2(acc[mt][nt][2], acc[mt][nt][3]);
                }
        }
        // slot-overwrite safety polls (1+ step of slack; overlap Ds staging)
        if (tid == 0 && t > 0)               poll_ge(&g_cnt[layer],     BPL * t);
        if (tid == 1 && layer < 3 && t >= 1) poll_ge(&g_cnt[layer + 1], BPL * (t - 1));
        __syncthreads();

        // tail prefetch: next step's weight chunks 0,1 (buf0/1 reads all done)
        stageA(smb, 0, 0, layer, blk);
        stageA(smb, 1, 1, layer, blk);
        CPC();

        // gates + h writes (thread owns (eu, 4 batches)); sum 2 wk partials
        const int slot_w = t & 1;
        #pragma unroll
        for (int j = 0; j < 4; ++j) {
            const int b = eb0 + j;
            float zi = bzi, zf = bzf, zg = bzg, zo = bzo;
            #pragma unroll
            for (int p = 0; p < 2; ++p) {
                const float* Dp = Ds + p * DSPLANE_F;
                zi += Dp[(eu * 4 + 0) * DPITCH + b];
                zf += Dp[(eu * 4 + 1) * DPITCH + b];
                zg += Dp[(eu * 4 + 2) * DPITCH + b];
                zo += Dp[(eu * 4 + 3) * DPITCH + b];
            }
            const float c = fsig(zf) * c_st[j] + fsig(zi) * ftanh_(zg);
            c_st[j] = c;
            const float h = fsig(zo) * ftanh_(c);
            unsigned short hh, hl;
            split2(h, hh, hl);
            g_acthi[layer][slot_w][b][kst + u0 + eu] = hh;
            g_actlo[layer][slot_w][b][kst + u0 + eu] = hl;
            if (layer < 3) {
                g_acthi[layer + 1][slot_w][b][u0 + eu] = hh;
                g_actlo[layer + 1][slot_w][b][u0 + eu] = hl;
            } else {
                g_h3[((size_t)b * SS + t) * HH + u0 + eu] = h;
            }
        }
        __syncthreads();
        if (tid == 0) {
            __threadfence();
            atomicAdd(&g_cg[layer][mygrp], 1);
            atomicAdd(&g_cnt[layer], 1);
        }
    }

    // ---------------- phase 2: LayerNorm + output projection ------------------
    if (tid == 0) poll_ge(&g_cnt[3], BPL * SS);
    __syncthreads();

    float* As3 = smf;
    float* Ws3 = smf + 512 * PAD;
    float* red = smf + 512 * PAD + 64 * PAD;
    const int lane2 = tid & 31, wrp = tid >> 5;
    const int tc  = tid & 15, tr = tid >> 4;
    const int lkk = tid & 63, lr0 = tid >> 6;

    for (int i = 0; i < 4; ++i) {
        const int base_row = bx * 256 + i * 64;

        for (int rr = 0; rr < 64; ++rr) {
            const size_t row = (size_t)base_row + rr;
            const float v0 = __ldcg(&g_h3[row * HH + tid]);
            const float v1 = __ldcg(&g_h3[row * HH + tid + 256]);
            float s = v0 + v1, s2 = v0 * v0 + v1 * v1;
            #pragma unroll
            for (int off = 16; off > 0; off >>= 1) {
                s  += __shfl_down_sync(0xffffffffu, s,  off);
                s2 += __shfl_down_sync(0xffffffffu, s2, off);
            }
            if (lane2 == 0) { red[wrp] = s; red[8 + wrp] = s2; }
            __syncthreads();
            if (tid == 0) {
                float S1 = 0.f, S2 = 0.f;
                for (int jj = 0; jj < 8; ++jj) { S1 += red[jj]; S2 += red[8 + jj]; }
                const float mu  = S1 * (1.0f / 512.0f);
                const float var = S2 * (1.0f / 512.0f) - mu * mu;
                red[16] = mu;
                red[17] = rsqrtf(var + 1e-5f);
            }
            __syncthreads();
            const float mu = red[16], rstd = red[17];
            As3[tid * PAD + rr]         = (v0 - mu) * rstd * lng[tid]       + lnb[tid];
            As3[(tid + 256) * PAD + rr] = (v1 - mu) * rstd * lng[tid + 256] + lnb[tid + 256];
            __syncthreads();
        }

        float acc2[4][4];
        #pragma unroll
        for (int r = 0; r < 4; ++r)
            #pragma unroll
            for (int g = 0; g < 4; ++g) acc2[r][g] = 0.0f;

        for (int ch = 0; ch < 8; ++ch) {
            #pragma unroll
            for (int p = 0; p < 16; ++p) {
                const int jc = p * 4 + lr0;
                Ws3[lkk * PAD + (jc & 15) * 4 + (jc >> 4)] =
                    Wo[(size_t)jc * HH + ch * 64 + lkk];
            }
            __syncthreads();
            #pragma unroll 16
            for (int kk = 0; kk < 64; ++kk) {
                const float4 a  = *(const float4*)(As3 + (ch * 64 + kk) * PAD + tr * 4);
                const float4 wv = *(const float4*)(Ws3 + kk * PAD + tc * 4);
                acc2[0][0] += a.x * wv.x; acc2[0][1] += a.x * wv.y;
                acc2[0][2] += a.x * wv.z; acc2[0][3] += a.x * wv.w;
                acc2[1][0] += a.y * wv.x; acc2[1][1] += a.y * wv.y;
                acc2[1][2] += a.y * wv.z; acc2[1][3] += a.y * wv.w;
                acc2[2][0] += a.z * wv.x; acc2[2][1] += a.z * wv.y;
                acc2[2][2] += a.z * wv.z; acc2[2][3] += a.z * wv.w;
                acc2[3][0] += a.w * wv.x; acc2[3][1] += a.w * wv.y;
                acc2[3][2] += a.w * wv.z; acc2[3][3] += a.w * wv.w;
            }
            __syncthreads();
        }

        #pragma unroll
        for (int r = 0; r < 4; ++r) {
            const size_t row = (size_t)base_row + tr * 4 + r;
            #pragma unroll
            for (int g = 0; g < 4; ++g) {
                const int d = g * 16 + tc;
                out[row * DOUT + d] = acc2[r][g] + bo[d];
            }
        }
        __syncthreads();
    }
}

extern "C" void kernel_launch(void* const* d_in, const int* in_sizes, int n_in,
                              void* d_out, int out_size) {
    const float* x   = (const float*)d_in[0];
    const float* W0  = (const float*)d_in[1];
    const float* b0  = (const float*)d_in[2];
    const float* W1  = (const float*)d_in[3];
    const float* b1  = (const float*)d_in[4];
    const float* W2  = (const float*)d_in[5];
    const float* b2  = (const float*)d_in[6];
    const float* W3  = (const float*)d_in[7];
    const float* b3  = (const float*)d_in[8];
    const float* lng = (const float*)d_in[9];
    const float* lnb = (const float*)d_in[10];
    const float* Wo  = (const float*)d_in[11];
    const float* bo  = (const float*)d_in[12];
    float* out = (float*)d_out;

    cudaFuncSetAttribute(lstm_mma_kernel,
                         cudaFuncAttributeMaxDynamicSharedMemorySize, SMEM_BYTES);
    lstm_mma_kernel<<<NB, NT, SMEM_BYTES>>>(
        x, W0, b0, W1, b1, W2, b2, W3, b3, lng, lnb, Wo, bo, out);
}

// round 13
// speedup vs baseline: 1.0607x; 1.0607x over previous
#include <cuda_runtime.h>
#include <cstdint>
#include <math.h>

// ---------------- problem constants ----------------
#define BB   64
#define SS   512
#define DIN  64
#define HH   512
#define NLAY 4
#define DOUT 64

// ---------------- config ----------------
#define NB   128         // 32 blocks per layer
#define NT   256         // 8 warps: 2(m) x 2(n) x 2(k)
#define BPL  32
#define UPB  16          // hidden units per block (64 gate rows)
#define KC   128         // K elements per chunk

// smem layout (phase 1), bytes
#define ROWB      272                 // bytes per operand row (256 data + 16 pad)
#define PLANE_B   17408               // 64 * 272
#define BUF_B     69632               // 4 planes: Ahi, Alo, Bhi, Blo
#define DS_OFF_F  34816               // float idx of Ds partials (= buf2 start)
#define DSPLANE_F 4352                // 64 * 68 floats per wk plane
#define DPITCH    68
#define PAD       68
#define SMEM_BYTES 208896             // 3 bufs; >= phase-2 need (156928)

// ---------------- persistent device state ----------------
__device__ unsigned short g_Whi[NLAY][2048][1024];    // pre-split weights, block-row order
__device__ unsigned short g_Wlo[NLAY][2048][1024];    // unwritten k stays 0
__device__ unsigned short g_acthi[NLAY][2][BB][1024]; // per-layer B operand planes
__device__ unsigned short g_actlo[NLAY][2][BB][1024];
__device__ unsigned short g_xhi[SS][BB][DIN];         // pre-split input
__device__ unsigned short g_xlo[SS][BB][DIN];
__device__ float g_h3[(size_t)BB * SS * HH];          // layer-3 h for phase 2
__device__ int g_cnt[NLAY];                           // per-layer wave progress
__device__ unsigned int g_arrive = 0;
__device__ unsigned int g_gen    = 0;

// ---------------- helpers ----------------
__device__ __forceinline__ uint32_t smem_u32(const void* p) {
    uint32_t a;
    asm("{ .reg .u64 t; cvta.to.shared.u64 t, %1; cvt.u32.u64 %0, t; }" : "=r"(a) : "l"(p));
    return a;
}
__device__ __forceinline__ unsigned short bf16rn(float v) {
    uint32_t u = __float_as_uint(v);
    uint32_t r = u + 0x7FFFu + ((u >> 16) & 1u);
    return (unsigned short)(r >> 16);
}
__device__ __forceinline__ void split2(float v, unsigned short& h, unsigned short& l) {
    h = bf16rn(v);
    float hf = __uint_as_float((uint32_t)h << 16);
    l = bf16rn(v - hf);
}
__device__ __forceinline__ float fsig(float x)   { return __fdividef(1.0f, 1.0f + __expf(-x)); }
__device__ __forceinline__ float ftanh_(float x) { return __fdividef(2.0f, 1.0f + __expf(-2.0f * x)) - 1.0f; }

__device__ __forceinline__ void poll_ge(int* p, int v) {
    int x;
    while (true) {
        asm volatile("ld.global.acquire.gpu.b32 %0, [%1];" : "=r"(x) : "l"(p) : "memory");
        if (x >= v) return;
        __nanosleep(32);
    }
}

__device__ __forceinline__ void mma_bf16(float* c, const uint32_t* a, const uint32_t* b) {
    asm volatile(
        "mma.sync.aligned.m16n8k16.row.col.f32.bf16.bf16.f32 "
        "{%0,%1,%2,%3}, {%4,%5,%6,%7}, {%8,%9}, {%0,%1,%2,%3};"
        : "+f"(c[0]), "+f"(c[1]), "+f"(c[2]), "+f"(c[3])
        : "r"(a[0]), "r"(a[1]), "r"(a[2]), "r"(a[3]), "r"(b[0]), "r"(b[1]));
}
__device__ __forceinline__ void ldsm4(uint32_t* r, uint32_t saddr) {
    asm volatile("ldmatrix.sync.aligned.m8n8.x4.shared.b16 {%0,%1,%2,%3}, [%4];"
                 : "=r"(r[0]), "=r"(r[1]), "=r"(r[2]), "=r"(r[3]) : "r"(saddr));
}
__device__ __forceinline__ void cp16(uint32_t d, const void* s) {
    asm volatile("cp.async.cg.shared.global [%0], [%1], 16;" :: "r"(d), "l"(s) : "memory");
}
#define CPC()  asm volatile("cp.async.commit_group;" ::: "memory")
#define CPW1() asm volatile("cp.async.wait_group 1;" ::: "memory")
#define CPW0() asm volatile("cp.async.wait_group 0;" ::: "memory")

__device__ __forceinline__ void gridbar(unsigned int& lgen) {
    __syncthreads();
    __threadfence();
    if (threadIdx.x == 0) {
        unsigned int old = atomicAdd(&g_arrive, 1u);
        if (((old + 1u) % NB) == 0u) {
            atomicAdd(&g_gen, 1u);
        } else {
            while (*((volatile unsigned int*)&g_gen) < lgen + 1u) { __nanosleep(32); }
        }
    }
    lgen += 1u;
    __syncthreads();
    __threadfence();
}

// ---- staging pieces (NT=256: j<4 covers a full 64x256B plane pair) ----
__device__ __forceinline__ void stageA(uint32_t smb, int buf, int ch, int layer, int blk) {
    const int tid = threadIdx.x;
    const uint32_t base = smb + (uint32_t)buf * BUF_B;
    #pragma unroll
    for (int j = 0; j < 4; ++j) {
        const int idx = tid + 256 * j, row = idx >> 4, q = idx & 15;
        const uint32_t d = base + (uint32_t)(row * ROWB + q * 16);
        const int k = ch * KC + q * 8;
        cp16(d,           &g_Whi[layer][blk * 64 + row][k]);
        cp16(d + PLANE_B, &g_Wlo[layer][blk * 64 + row][k]);
    }
}
__device__ __forceinline__ void stageB(uint32_t smb, int buf, int ch, int layer,
                                       int t, int Kin) {
    const int tid = threadIdx.x;
    const uint32_t base = smb + (uint32_t)buf * BUF_B;
    #pragma unroll
    for (int j = 0; j < 4; ++j) {
        const int idx = tid + 256 * j, n = idx >> 4, q = idx & 15;
        const uint32_t d = base + 2u * PLANE_B + (uint32_t)(n * ROWB + q * 16);
        const int k = ch * KC + q * 8;
        const unsigned short *sh, *sl;
        if (layer == 0 && k < DIN) {
            sh = &g_xhi[t][n][k];
            sl = &g_xlo[t][n][k];
        } else {
            const int slot = (k < Kin) ? (t & 1) : ((t & 1) ^ 1);
            sh = &g_acthi[layer][slot][n][k];
            sl = &g_actlo[layer][slot][n][k];
        }
        cp16(d, sh);
        cp16(d + PLANE_B, sl);
    }
}

__global__ void __launch_bounds__(NT, 1) lstm_mma_kernel(
    const float* __restrict__ x,
    const float* __restrict__ W0, const float* __restrict__ b0,
    const float* __restrict__ W1, const float* __restrict__ b1,
    const float* __restrict__ W2, const float* __restrict__ b2,
    const float* __restrict__ W3, const float* __restrict__ b3,
    const float* __restrict__ lng, const float* __restrict__ lnb,
    const float* __restrict__ Wo,  const float* __restrict__ bo,
    float* __restrict__ out)
{
    extern __shared__ char smc[];
    float* smf = (float*)smc;
    const int tid = threadIdx.x;
    const int bx  = blockIdx.x;
    unsigned int lgen = *((volatile unsigned int*)&g_gen);
    const uint32_t smb = smem_u32(smc);

    const float* Wsrc[4] = {W0, W1, W2, W3};
    const float* bsrc[4] = {b0, b1, b2, b3};

    // ---------------- phase 0: reset, zero act planes, split W and x ----------
    if (bx == 0 && tid < 4) g_cnt[tid] = 0;
    {
        uint4 z = make_uint4(0, 0, 0, 0);
        uint4* ph = (uint4*)&g_acthi[0][0][0][0];
        uint4* pl = (uint4*)&g_actlo[0][0][0][0];
        const int n16 = NLAY * 2 * BB * 1024 * 2 / 16;
        for (int i = bx * NT + tid; i < n16; i += NB * NT) { ph[i] = z; pl[i] = z; }
    }
    {
        for (int rr = 0; rr < 64; ++rr) {
            const int gr = bx * 64 + rr;
            const int l = gr >> 11, r = gr & 2047;
            const int blk2 = r >> 6, rloc = r & 63, iu = rloc >> 2, g = rloc & 3;
            const int fanin = (l == 0) ? (DIN + HH) : (2 * HH);
            const float* src = Wsrc[l] + (size_t)(g * HH + blk2 * UPB + iu) * fanin;
            const int k = tid * 4;
            if (k < fanin) {
                float4 v = __ldg((const float4*)(src + k));
                unsigned short h0, l0, h1, l1, h2, l2, h3, l3;
                split2(v.x, h0, l0); split2(v.y, h1, l1);
                split2(v.z, h2, l2); split2(v.w, h3, l3);
                // layer 0: own-h columns relocated by +64 (pad [64,128) stays zero)
                const int kk = (l == 0 && k >= DIN) ? k + 64 : k;
                *(uint2*)&g_Whi[l][r][kk] =
                    make_uint2((uint32_t)h0 | ((uint32_t)h1 << 16), (uint32_t)h2 | ((uint32_t)h3 << 16));
                *(uint2*)&g_Wlo[l][r][kk] =
                    make_uint2((uint32_t)l0 | ((uint32_t)l1 << 16), (uint32_t)l2 | ((uint32_t)l3 << 16));
            }
        }
    }
    {
        for (int i = bx * NT + tid; i < SS * BB * (DIN / 2); i += NB * NT) {
            const int k2 = i & 31, n = (i >> 5) & 63, tt = i >> 11;
            float2 v = __ldg((const float2*)&x[((size_t)n * SS + tt) * DIN + k2 * 2]);
            unsigned short h0, l0, h1, l1;
            split2(v.x, h0, l0); split2(v.y, h1, l1);
            *(uint32_t*)&g_xhi[tt][n][k2 * 2] = (uint32_t)h0 | ((uint32_t)h1 << 16);
            *(uint32_t*)&g_xlo[tt][n][k2 * 2] = (uint32_t)l0 | ((uint32_t)l1 << 16);
        }
    }
    gridbar(lgen);

    // ---------------- phase 1: wavefront LSTM, slack-positioned own poll ------
    const int layer = bx >> 5;
    const int blk   = bx & 31;
    const int u0    = blk * UPB;
    const float* bl = bsrc[layer];
    const int Kin   = (layer == 0) ? DIN : HH;
    const int kst   = (layer == 0) ? 128 : 512;   // own-h store offset
    const int nch   = (layer == 0) ? 5 : 8;

    const int lane = tid & 31, wid = tid >> 5;
    const int wm = wid & 1, wn = (wid >> 1) & 1, wk = wid >> 2;  // 2x2x2

    const uint32_t aoff0 = (uint32_t)((wm * 32 + (lane & 15)) * ROWB + (lane >> 4) * 16);
    const uint32_t aoff1 = aoff0 + 16u * ROWB;
    const uint32_t boff0 = 2u * PLANE_B +
        (uint32_t)((wn * 32 + (lane & 7) + ((lane >> 4) << 3)) * ROWB + (((lane >> 3) & 1) << 4));
    const uint32_t boff1 = boff0 + 16u * ROWB;
    const uint32_t ksb0 = (uint32_t)(wk * 4) * 32u;   // k-half start

    const int eu  = tid >> 4;                   // epilogue unit 0..15
    const int eb0 = (tid & 15) * 4;             // epilogue batch base (4 each)
    const float bzi = __ldg(&bl[0 * HH + u0 + eu]);
    const float bzf = __ldg(&bl[1 * HH + u0 + eu]);
    const float bzg = __ldg(&bl[2 * HH + u0 + eu]);
    const float bzo = __ldg(&bl[3 * HH + u0 + eu]);
    float c_st[4] = {0.f, 0.f, 0.f, 0.f};

    float* Ds = smf + DS_OFF_F;                 // 2 partial planes (per wk) in buf2

    // initial AA: weight chunks 0,1 for step 0 (one commit group)
    stageA(smb, 0, 0, layer, blk);
    stageA(smb, 1, 1, layer, blk);
    CPC();

    for (int t = 0; t < SS; ++t) {
        // step-start polls: prev-layer (a period of slack, near-instant);
        // layer 0 needs own h at chunk 1 so it polls here too
        if (tid == 0) {
            if (layer > 0)      poll_ge(&g_cnt[layer - 1], BPL * (t + 1));
            else if (t > 0)     poll_ge(&g_cnt[0], BPL * t);
        }
        __syncthreads();

        // acts for chunks 0,1 (two separate groups)
        stageB(smb, 0, 0, layer, t, Kin); CPC();
        stageB(smb, 1, 1, layer, t, Kin); CPC();

        float acc[2][4][4];
        #pragma unroll
        for (int mt = 0; mt < 2; ++mt)
            #pragma unroll
            for (int nt = 0; nt < 4; ++nt)
                #pragma unroll
                for (int q = 0; q < 4; ++q) acc[mt][nt][q] = 0.f;

        for (int ch = 0; ch < nch; ++ch) {
            if (ch == nch - 1) { CPW0(); } else { CPW1(); }
            // own-layer h(t-1) first consumed via chunk 4 (staged this iteration):
            // poll here, with chunks 0-3 of compute as built-in slack
            if (ch == 2 && layer > 0 && t > 0 && tid == 0)
                poll_ge(&g_cnt[layer], BPL * t);
            __syncthreads();                    // chunk ch ready; prior buffer free
            if (ch + 2 < nch) {
                const int b2 = (ch + 2) % 3;
                stageA(smb, b2, ch + 2, layer, blk);
                stageB(smb, b2, ch + 2, layer, t, Kin);
                CPC();
            }

            const uint32_t bb = smb + (uint32_t)(ch % 3) * BUF_B;
            #pragma unroll
            for (int ks0 = 0; ks0 < 4; ++ks0) {
                const uint32_t kb = ksb0 + (uint32_t)ks0 * 32u;
                uint32_t ah0[4], ah1[4], al0[4], al1[4];
                uint32_t bh0[4], bh1[4], bl0[4], bl1[4];
                ldsm4(ah0, bb + aoff0 + kb);
                ldsm4(ah1, bb + aoff1 + kb);
                ldsm4(al0, bb + aoff0 + PLANE_B + kb);
                ldsm4(al1, bb + aoff1 + PLANE_B + kb);
                ldsm4(bh0, bb + boff0 + kb);
                ldsm4(bh1, bb + boff1 + kb);
                ldsm4(bl0, bb + boff0 + PLANE_B + kb);
                ldsm4(bl1, bb + boff1 + PLANE_B + kb);
                const uint32_t* bhv[4] = {bh0, bh0 + 2, bh1, bh1 + 2};
                const uint32_t* blv[4] = {bl0, bl0 + 2, bl1, bl1 + 2};
                #pragma unroll
                for (int nt = 0; nt < 4; ++nt) {
                    mma_bf16(acc[0][nt], ah0, bhv[nt]);
                    mma_bf16(acc[0][nt], ah0, blv[nt]);
                    mma_bf16(acc[0][nt], al0, bhv[nt]);
                    mma_bf16(acc[1][nt], ah1, bhv[nt]);
                    mma_bf16(acc[1][nt], ah1, blv[nt]);
                    mma_bf16(acc[1][nt], al1, bhv[nt]);
                }
            }
        }

        // each k-half warp group writes its own partial plane (no RMW, 1 sync)
        {
            float* Dp = Ds + wk * DSPLANE_F;
            const int r = lane >> 2, cp2 = (lane & 3) * 2;
            #pragma unroll
            for (int mt = 0; mt < 2; ++mt)
                #pragma unroll
                for (int nt = 0; nt < 4; ++nt) {
                    const int row = wm * 32 + mt * 16 + r;
                    const int col = wn * 32 + nt * 8 + cp2;
                    *(float2*)&Dp[row * DPITCH + col] =
                        make_float2(acc[mt][nt][0], acc[mt][nt][1]);
                    *(float2*)&Dp[(row + 8) * DPITCH + col] =
                        make_float2(acc[mt][nt][2], acc[mt][nt][3]);
                }
        }
        // slot-overwrite safety poll for next layer (>=1 step of slack here)
        if (tid == 1 && layer < 3 && t >= 1) poll_ge(&g_cnt[layer + 1], BPL * (t - 1));
        __syncthreads();

        // tail prefetch: next step's weight chunks 0,1 (buf0/1 reads all done)
        stageA(smb, 0, 0, layer, blk);
        stageA(smb, 1, 1, layer, blk);
        CPC();

        // gates + h writes (thread owns (eu, 4 batches)); sum 2 wk partials
        const int slot_w = t & 1;
        #pragma unroll
        for (int j = 0; j < 4; ++j) {
            const int b = eb0 + j;
            float zi = bzi, zf = bzf, zg = bzg, zo = bzo;
            #pragma unroll
            for (int p = 0; p < 2; ++p) {
                const float* Dp = Ds + p * DSPLANE_F;
                zi += Dp[(eu * 4 + 0) * DPITCH + b];
                zf += Dp[(eu * 4 + 1) * DPITCH + b];
                zg += Dp[(eu * 4 + 2) * DPITCH + b];
                zo += Dp[(eu * 4 + 3) * DPITCH + b];
            }
            const float c = fsig(zf) * c_st[j] + fsig(zi) * ftanh_(zg);
            c_st[j] = c;
            const float h = fsig(zo) * ftanh_(c);
            unsigned short hh, hl;
            split2(h, hh, hl);
            g_acthi[layer][slot_w][b][kst + u0 + eu] = hh;
            g_actlo[layer][slot_w][b][kst + u0 + eu] = hl;
            if (layer < 3) {
                g_acthi[layer + 1][slot_w][b][u0 + eu] = hh;
                g_actlo[layer + 1][slot_w][b][u0 + eu] = hl;
            } else {
                g_h3[((size_t)b * SS + t) * HH + u0 + eu] = h;
            }
        }
        __syncthreads();
        if (tid == 0) {
            __threadfence();
            atomicAdd(&g_cnt[layer], 1);
        }
    }

    // ---------------- phase 2: LayerNorm + output projection ------------------
    if (tid == 0) poll_ge(&g_cnt[3], BPL * SS);
    __syncthreads();

    float* As3 = smf;
    float* Ws3 = smf + 512 * PAD;
    float* red = smf + 512 * PAD + 64 * PAD;
    const int lane2 = tid & 31, wrp = tid >> 5;
    const int tc  = tid & 15, tr = tid >> 4;
    const int lkk = tid & 63, lr0 = tid >> 6;

    for (int i = 0; i < 4; ++i) {
        const int base_row = bx * 256 + i * 64;

        for (int rr = 0; rr < 64; ++rr) {
            const size_t row = (size_t)base_row + rr;
            const float v0 = __ldcg(&g_h3[row * HH + tid]);
            const float v1 = __ldcg(&g_h3[row * HH + tid + 256]);
            float s = v0 + v1, s2 = v0 * v0 + v1 * v1;
            #pragma unroll
            for (int off = 16; off > 0; off >>= 1) {
                s  += __shfl_down_sync(0xffffffffu, s,  off);
                s2 += __shfl_down_sync(0xffffffffu, s2, off);
            }
            if (lane2 == 0) { red[wrp] = s; red[8 + wrp] = s2; }
            __syncthreads();
            if (tid == 0) {
                float S1 = 0.f, S2 = 0.f;
                for (int jj = 0; jj < 8; ++jj) { S1 += red[jj]; S2 += red[8 + jj]; }
                const float mu  = S1 * (1.0f / 512.0f);
                const float var = S2 * (1.0f / 512.0f) - mu * mu;
                red[16] = mu;
                red[17] = rsqrtf(var + 1e-5f);
            }
            __syncthreads();
            const float mu = red[16], rstd = red[17];
            As3[tid * PAD + rr]         = (v0 - mu) * rstd * lng[tid]       + lnb[tid];
            As3[(tid + 256) * PAD + rr] = (v1 - mu) * rstd * lng[tid + 256] + lnb[tid + 256];
            __syncthreads();
        }

        float acc2[4][4];
        #pragma unroll
        for (int r = 0; r < 4; ++r)
            #pragma unroll
            for (int g = 0; g < 4; ++g) acc2[r][g] = 0.0f;

        for (int ch = 0; ch < 8; ++ch) {
            #pragma unroll
            for (int p = 0; p < 16; ++p) {
                const int jc = p * 4 + lr0;
                Ws3[lkk * PAD + (jc & 15) * 4 + (jc >> 4)] =
                    Wo[(size_t)jc * HH + ch * 64 + lkk];
            }
            __syncthreads();
            #pragma unroll 16
            for (int kk = 0; kk < 64; ++kk) {
                const float4 a  = *(const float4*)(As3 + (ch * 64 + kk) * PAD + tr * 4);
                const float4 wv = *(const float4*)(Ws3 + kk * PAD + tc * 4);
                acc2[0][0] += a.x * wv.x; acc2[0][1] += a.x * wv.y;
                acc2[0][2] += a.x * wv.z; acc2[0][3] += a.x * wv.w;
                acc2[1][0] += a.y * wv.x; acc2[1][1] += a.y * wv.y;
                acc2[1][2] += a.y * wv.z; acc2[1][3] += a.y * wv.w;
                acc2[2][0] += a.z * wv.x; acc2[2][1] += a.z * wv.y;
                acc2[2][2] += a.z * wv.z; acc2[2][3] += a.z * wv.w;
                acc2[3][0] += a.w * wv.x; acc2[3][1] += a.w * wv.y;
                acc2[3][2] += a.w * wv.z; acc2[3][3] += a.w * wv.w;
            }
            __syncthreads();
        }

        #pragma unroll
        for (int r = 0; r < 4; ++r) {
            const size_t row = (size_t)base_row + tr * 4 + r;
            #pragma unroll
            for (int g = 0; g < 4; ++g) {
                const int d = g * 16 + tc;
                out[row * DOUT + d] = acc2[r][g] + bo[d];
            }
        }
        __syncthreads();
    }
}

extern "C" void kernel_launch(void* const* d_in, const int* in_sizes, int n_in,
                              void* d_out, int out_size) {
    const float* x   = (const float*)d_in[0];
    const float* W0  = (const float*)d_in[1];
    const float* b0  = (const float*)d_in[2];
    const float* W1  = (const float*)d_in[3];
    const float* b1  = (const float*)d_in[4];
    const float* W2  = (const float*)d_in[5];
    const float* b2  = (const float*)d_in[6];
    const float* W3  = (const float*)d_in[7];
    const float* b3  = (const float*)d_in[8];
    const float* lng = (const float*)d_in[9];
    const float* lnb = (const float*)d_in[10];
    const float* Wo  = (const float*)d_in[11];
    const float* bo  = (const float*)d_in[12];
    float* out = (float*)d_out;

    cudaFuncSetAttribute(lstm_mma_kernel,
                         cudaFuncAttributeMaxDynamicSharedMemorySize, SMEM_BYTES);
    lstm_mma_kernel<<<NB, NT, SMEM_BYTES>>>(
        x, W0, b0, W1, b1, W2, b2, W3, b3, lng, lnb, Wo, bo, out);
}

// round 15
// speedup vs baseline: 1.4549x; 1.3716x over previous
#include <cuda_runtime.h>
#include <cstdint>
#include <math.h>

// ---------------- problem constants ----------------
#define BB   64
#define SS   512
#define DIN  64
#define HH   512
#define NLAY 4
#define DOUT 64

// ---------------- config ----------------
#define NB   128         // 32 blocks per layer
#define NT   320         // 8 consumer warps (2m x 2n x 2k) + 2 producer warps
#define BPL  32
#define UPB  16          // hidden units per block (64 gate rows)
#define KC   128         // K elements per chunk

// smem layout (phase 1), bytes
#define ROWB      272                 // bytes per operand row (256 data + 16 pad)
#define PLANE_B   17408               // 64 * 272
#define BUF_B     69632               // 4 planes: Ahi, Alo, Bhi, Blo
#define DS_OFF_F  34816               // float idx of Ds partials (byte 139264)
#define DSPLANE_F 4352                // 64 * 68 floats per wk plane
#define DPITCH    68
#define PAD       68
#define MB_OFF    174080              // 4 mbarriers (8B each)
#define SMEM_BYTES 174144

// ---------------- persistent device state ----------------
__device__ unsigned short g_Whi[NLAY][2048][1024];    // pre-split weights, block-row order
__device__ unsigned short g_Wlo[NLAY][2048][1024];    // unwritten k stays 0
__device__ unsigned short g_acthi[NLAY][2][BB][1024]; // per-layer B operand planes
__device__ unsigned short g_actlo[NLAY][2][BB][1024];
__device__ unsigned short g_xhi[SS][BB][DIN];         // pre-split input
__device__ unsigned short g_xlo[SS][BB][DIN];
__device__ float g_h3[(size_t)BB * SS * HH];          // layer-3 h for phase 2
__device__ int g_cnt[NLAY];                           // per-layer wave progress
__device__ unsigned int g_arrive = 0;
__device__ unsigned int g_gen    = 0;

// ---------------- helpers ----------------
__device__ __forceinline__ uint32_t smem_u32(const void* p) {
    uint32_t a;
    asm("{ .reg .u64 t; cvta.to.shared.u64 t, %1; cvt.u32.u64 %0, t; }" : "=r"(a) : "l"(p));
    return a;
}
__device__ __forceinline__ unsigned short bf16rn(float v) {
    uint32_t u = __float_as_uint(v);
    uint32_t r = u + 0x7FFFu + ((u >> 16) & 1u);
    return (unsigned short)(r >> 16);
}
__device__ __forceinline__ void split2(float v, unsigned short& h, unsigned short& l) {
    h = bf16rn(v);
    float hf = __uint_as_float((uint32_t)h << 16);
    l = bf16rn(v - hf);
}
__device__ __forceinline__ float fsig(float x)   { return __fdividef(1.0f, 1.0f + __expf(-x)); }
__device__ __forceinline__ float ftanh_(float x) { return __fdividef(2.0f, 1.0f + __expf(-2.0f * x)) - 1.0f; }

__device__ __forceinline__ void poll_ge(int* p, int v) {
    int x;
    while (true) {
        asm volatile("ld.global.acquire.gpu.b32 %0, [%1];" : "=r"(x) : "l"(p) : "memory");
        if (x >= v) return;
        __nanosleep(32);
    }
}

__device__ __forceinline__ void mma_bf16(float* c, const uint32_t* a, const uint32_t* b) {
    asm volatile(
        "mma.sync.aligned.m16n8k16.row.col.f32.bf16.bf16.f32 "
        "{%0,%1,%2,%3}, {%4,%5,%6,%7}, {%8,%9}, {%0,%1,%2,%3};"
        : "+f"(c[0]), "+f"(c[1]), "+f"(c[2]), "+f"(c[3])
        : "r"(a[0]), "r"(a[1]), "r"(a[2]), "r"(a[3]), "r"(b[0]), "r"(b[1]));
}
__device__ __forceinline__ void ldsm4(uint32_t* r, uint32_t saddr) {
    asm volatile("ldmatrix.sync.aligned.m8n8.x4.shared.b16 {%0,%1,%2,%3}, [%4];"
                 : "=r"(r[0]), "=r"(r[1]), "=r"(r[2]), "=r"(r[3]) : "r"(saddr));
}
__device__ __forceinline__ void cp16(uint32_t d, const void* s) {
    asm volatile("cp.async.cg.shared.global [%0], [%1], 16;" :: "r"(d), "l"(s) : "memory");
}

// ---- mbarrier primitives (baseline PTX, sm_80+) ----
#define MBINIT(addr, cnt) \
    asm volatile("mbarrier.init.shared::cta.b64 [%0], %1;" :: "r"(addr), "r"((uint32_t)(cnt)) : "memory")
#define MBARR(addr) \
    asm volatile("{\n\t.reg .b64 st;\n\tmbarrier.arrive.shared::cta.b64 st, [%0];\n\t}" \
                 :: "r"(addr) : "memory")
// .noinc: async completion DECREMENTS the initialized count (R14 bug: default
// variant is net-zero against the count -> full barrier never completed -> hang)
#define CPARRIVE(addr) \
    asm volatile("cp.async.mbarrier.arrive.noinc.shared::cta.b64 [%0];" :: "r"(addr) : "memory")
#define MBWAIT(addr, ph) do { \
    uint32_t done_; \
    do { \
        asm volatile("{\n\t.reg .pred p;\n\t" \
            "mbarrier.try_wait.parity.shared::cta.b64 p, [%1], %2;\n\t" \
            "selp.b32 %0, 1, 0, p;\n\t}" \
            : "=r"(done_) : "r"(addr), "r"((uint32_t)(ph)) : "memory"); \
    } while (!done_); \
} while (0)

#define BAR1() asm volatile("bar.sync 1, 256;" ::: "memory")   // consumers
#define BAR2() asm volatile("bar.sync 2, 64;"  ::: "memory")   // producers

__device__ __forceinline__ void gridbar(unsigned int& lgen) {
    __syncthreads();
    __threadfence();
    if (threadIdx.x == 0) {
        unsigned int old = atomicAdd(&g_arrive, 1u);
        if (((old + 1u) % NB) == 0u) {
            atomicAdd(&g_gen, 1u);
        } else {
            while (*((volatile unsigned int*)&g_gen) < lgen + 1u) { __nanosleep(32); }
        }
    }
    lgen += 1u;
    __syncthreads();
    __threadfence();
}

// ---- producer staging (64 threads, ptid in [0,64)) ----
__device__ __forceinline__ void stageA64(uint32_t smb, int buf, int ch, int layer,
                                         int blk, int ptid) {
    const uint32_t base = smb + (uint32_t)buf * BUF_B;
    #pragma unroll
    for (int j = 0; j < 16; ++j) {
        const int idx = ptid + 64 * j, row = idx >> 4, q = idx & 15;
        const uint32_t d = base + (uint32_t)(row * ROWB + q * 16);
        const int k = ch * KC + q * 8;
        cp16(d,           &g_Whi[layer][blk * 64 + row][k]);
        cp16(d + PLANE_B, &g_Wlo[layer][blk * 64 + row][k]);
    }
}
__device__ __forceinline__ void stageB64(uint32_t smb, int buf, int ch, int layer,
                                         int t, int Kin, int ptid) {
    const uint32_t base = smb + (uint32_t)buf * BUF_B;
    #pragma unroll
    for (int j = 0; j < 16; ++j) {
        const int idx = ptid + 64 * j, n = idx >> 4, q = idx & 15;
        const uint32_t d = base + 2u * PLANE_B + (uint32_t)(n * ROWB + q * 16);
        const int k = ch * KC + q * 8;
        const unsigned short *sh, *sl;
        if (layer == 0 && k < DIN) {
            sh = &g_xhi[t][n][k];
            sl = &g_xlo[t][n][k];
        } else {
            const int slot = (k < Kin) ? (t & 1) : ((t & 1) ^ 1);
            sh = &g_acthi[layer][slot][n][k];
            sl = &g_actlo[layer][slot][n][k];
        }
        cp16(d, sh);
        cp16(d + PLANE_B, sl);
    }
}

__global__ void __launch_bounds__(NT, 1) lstm_mma_kernel(
    const float* __restrict__ x,
    const float* __restrict__ W0, const float* __restrict__ b0,
    const float* __restrict__ W1, const float* __restrict__ b1,
    const float* __restrict__ W2, const float* __restrict__ b2,
    const float* __restrict__ W3, const float* __restrict__ b3,
    const float* __restrict__ lng, const float* __restrict__ lnb,
    const float* __restrict__ Wo,  const float* __restrict__ bo,
    float* __restrict__ out)
{
    extern __shared__ char smc[];
    float* smf = (float*)smc;
    const int tid = threadIdx.x;
    const int bx  = blockIdx.x;
    unsigned int lgen = *((volatile unsigned int*)&g_gen);
    const uint32_t smb = smem_u32(smc);
    const uint32_t mbF0 = smb + MB_OFF,      mbF1 = smb + MB_OFF + 8;
    const uint32_t mbE0 = smb + MB_OFF + 16, mbE1 = smb + MB_OFF + 24;

    const float* Wsrc[4] = {W0, W1, W2, W3};
    const float* bsrc[4] = {b0, b1, b2, b3};

    // ---------------- phase 0: reset, init mbarriers, split W and x ----------
    if (tid == 0) {
        MBINIT(mbF0, 64); MBINIT(mbF1, 64);   // producer cp-arrivals (.noinc)
        MBINIT(mbE0, 8);  MBINIT(mbE1, 8);    // consumer warp arrivals
    }
    if (bx == 0 && tid < 4) g_cnt[tid] = 0;
    {
        uint4 z = make_uint4(0, 0, 0, 0);
        uint4* ph = (uint4*)&g_acthi[0][0][0][0];
        uint4* pl = (uint4*)&g_actlo[0][0][0][0];
        const int n16 = NLAY * 2 * BB * 1024 * 2 / 16;
        for (int i = bx * NT + tid; i < n16; i += NB * NT) { ph[i] = z; pl[i] = z; }
    }
    {
        for (int rr = 0; rr < 64; ++rr) {
            const int gr = bx * 64 + rr;
            const int l = gr >> 11, r = gr & 2047;
            const int blk2 = r >> 6, rloc = r & 63, iu = rloc >> 2, g = rloc & 3;
            const int fanin = (l == 0) ? (DIN + HH) : (2 * HH);
            const float* src = Wsrc[l] + (size_t)(g * HH + blk2 * UPB + iu) * fanin;
            const int k = tid * 4;
            if (k < fanin) {
                float4 v = __ldg((const float4*)(src + k));
                unsigned short h0, l0, h1, l1, h2, l2, h3, l3;
                split2(v.x, h0, l0); split2(v.y, h1, l1);
                split2(v.z, h2, l2); split2(v.w, h3, l3);
                // layer 0: own-h columns relocated by +64 (pad [64,128) stays zero)
                const int kk = (l == 0 && k >= DIN) ? k + 64 : k;
                *(uint2*)&g_Whi[l][r][kk] =
                    make_uint2((uint32_t)h0 | ((uint32_t)h1 << 16), (uint32_t)h2 | ((uint32_t)h3 << 16));
                *(uint2*)&g_Wlo[l][r][kk] =
                    make_uint2((uint32_t)l0 | ((uint32_t)l1 << 16), (uint32_t)l2 | ((uint32_t)l3 << 16));
            }
        }
    }
    {
        for (int i = bx * NT + tid; i < SS * BB * (DIN / 2); i += NB * NT) {
            const int k2 = i & 31, n = (i >> 5) & 63, tt = i >> 11;
            float2 v = __ldg((const float2*)&x[((size_t)n * SS + tt) * DIN + k2 * 2]);
            unsigned short h0, l0, h1, l1;
            split2(v.x, h0, l0); split2(v.y, h1, l1);
            *(uint32_t*)&g_xhi[tt][n][k2 * 2] = (uint32_t)h0 | ((uint32_t)h1 << 16);
            *(uint32_t*)&g_xlo[tt][n][k2 * 2] = (uint32_t)l0 | ((uint32_t)l1 << 16);
        }
    }
    gridbar(lgen);

    // ---------------- phase 1: producer/consumer wavefront LSTM ---------------
    const int layer = bx >> 5;
    const int blk   = bx & 31;
    const int u0    = blk * UPB;
    const float* bl = bsrc[layer];
    const int Kin   = (layer == 0) ? DIN : HH;
    const int kst   = (layer == 0) ? 128 : 512;   // own-h store offset
    const int nch   = (layer == 0) ? 5 : 8;
    const int ownStart = (layer == 0) ? 1 : 4;    // first chunk touching own h(t-1)

    const int lane = tid & 31, wid = tid >> 5;

    if (wid < 8) {
        // =================== CONSUMERS (8 warps, tid < 256) ===================
        const int wm = wid & 1, wn = (wid >> 1) & 1, wk = wid >> 2;  // 2x2x2

        const uint32_t aoff0 = (uint32_t)((wm * 32 + (lane & 15)) * ROWB + (lane >> 4) * 16);
        const uint32_t aoff1 = aoff0 + 16u * ROWB;
        const uint32_t boff0 = 2u * PLANE_B +
            (uint32_t)((wn * 32 + (lane & 7) + ((lane >> 4) << 3)) * ROWB + (((lane >> 3) & 1) << 4));
        const uint32_t boff1 = boff0 + 16u * ROWB;
        const uint32_t ksb0 = (uint32_t)(wk * 4) * 32u;   // k-half start

        const int eu  = tid >> 4;                 // epilogue unit 0..15
        const int eb0 = (tid & 15) * 4;           // epilogue batch base (4 each)
        const float bzi = __ldg(&bl[0 * HH + u0 + eu]);
        const float bzf = __ldg(&bl[1 * HH + u0 + eu]);
        const float bzg = __ldg(&bl[2 * HH + u0 + eu]);
        const float bzo = __ldg(&bl[3 * HH + u0 + eu]);
        float c_st[4] = {0.f, 0.f, 0.f, 0.f};

        float* Ds = smf + DS_OFF_F;
        int cg = 0;                               // global chunk cursor

        for (int t = 0; t < SS; ++t) {
            float acc[2][4][4];
            #pragma unroll
            for (int mt = 0; mt < 2; ++mt)
                #pragma unroll
                for (int nt = 0; nt < 4; ++nt)
                    #pragma unroll
                    for (int q = 0; q < 4; ++q) acc[mt][nt][q] = 0.f;

            for (int ch = 0; ch < nch; ++ch) {
                const int b = cg & 1, ph = (cg >> 1) & 1;
                MBWAIT((b ? mbF1 : mbF0), ph);

                const uint32_t bb = smb + (uint32_t)b * BUF_B;
                #pragma unroll
                for (int ks0 = 0; ks0 < 4; ++ks0) {
                    const uint32_t kb = ksb0 + (uint32_t)ks0 * 32u;
                    uint32_t ah0[4], ah1[4], al0[4], al1[4];
                    uint32_t bh0[4], bh1[4], bl0[4], bl1[4];
                    ldsm4(ah0, bb + aoff0 + kb);
                    ldsm4(ah1, bb + aoff1 + kb);
                    ldsm4(al0, bb + aoff0 + PLANE_B + kb);
                    ldsm4(al1, bb + aoff1 + PLANE_B + kb);
                    ldsm4(bh0, bb + boff0 + kb);
                    ldsm4(bh1, bb + boff1 + kb);
                    ldsm4(bl0, bb + boff0 + PLANE_B + kb);
                    ldsm4(bl1, bb + boff1 + PLANE_B + kb);
                    const uint32_t* bhv[4] = {bh0, bh0 + 2, bh1, bh1 + 2};
                    const uint32_t* blv[4] = {bl0, bl0 + 2, bl1, bl1 + 2};
                    #pragma unroll
                    for (int nt = 0; nt < 4; ++nt) {
                        mma_bf16(acc[0][nt], ah0, bhv[nt]);
                        mma_bf16(acc[0][nt], ah0, blv[nt]);
                        mma_bf16(acc[0][nt], al0, bhv[nt]);
                        mma_bf16(acc[1][nt], ah1, bhv[nt]);
                        mma_bf16(acc[1][nt], ah1, blv[nt]);
                        mma_bf16(acc[1][nt], al1, bhv[nt]);
                    }
                }
                if (lane == 0) MBARR((b ? mbE1 : mbE0));
                ++cg;
            }

            // k-half partial planes (no RMW)
            {
                float* Dp = Ds + wk * DSPLANE_F;
                const int r = lane >> 2, cp2 = (lane & 3) * 2;
                #pragma unroll
                for (int mt = 0; mt < 2; ++mt)
                    #pragma unroll
                    for (int nt = 0; nt < 4; ++nt) {
                        const int row = wm * 32 + mt * 16 + r;
                        const int col = wn * 32 + nt * 8 + cp2;
                        *(float2*)&Dp[row * DPITCH + col] =
                            make_float2(acc[mt][nt][0], acc[mt][nt][1]);
                        *(float2*)&Dp[(row + 8) * DPITCH + col] =
                            make_float2(acc[mt][nt][2], acc[mt][nt][3]);
                    }
            }
            BAR1();
            // next-layer slot-overwrite safety (>=1 step of slack)
            if (tid == 0 && layer < 3 && t >= 1) poll_ge(&g_cnt[layer + 1], BPL * (t - 1));
            BAR1();

            // gates + h writes (thread owns (eu, 4 batches)); sum 2 wk partials
            const int slot_w = t & 1;
            #pragma unroll
            for (int j = 0; j < 4; ++j) {
                const int b2 = eb0 + j;
                float zi = bzi, zf = bzf, zg = bzg, zo = bzo;
                #pragma unroll
                for (int p = 0; p < 2; ++p) {
                    const float* Dp = Ds + p * DSPLANE_F;
                    zi += Dp[(eu * 4 + 0) * DPITCH + b2];
                    zf += Dp[(eu * 4 + 1) * DPITCH + b2];
                    zg += Dp[(eu * 4 + 2) * DPITCH + b2];
                    zo += Dp[(eu * 4 + 3) * DPITCH + b2];
                }
                const float c = fsig(zf) * c_st[j] + fsig(zi) * ftanh_(zg);
                c_st[j] = c;
                const float h = fsig(zo) * ftanh_(c);
                unsigned short hh, hl;
                split2(h, hh, hl);
                g_acthi[layer][slot_w][b2][kst + u0 + eu] = hh;
                g_actlo[layer][slot_w][b2][kst + u0 + eu] = hl;
                if (layer < 3) {
                    g_acthi[layer + 1][slot_w][b2][u0 + eu] = hh;
                    g_actlo[layer + 1][slot_w][b2][u0 + eu] = hl;
                } else {
                    g_h3[((size_t)b2 * SS + t) * HH + u0 + eu] = h;
                }
            }
            BAR1();
            if (tid == 0) {
                __threadfence();
                atomicAdd(&g_cnt[layer], 1);
            }
        }
    } else {
        // =================== PRODUCERS (2 warps, tid >= 256) ==================
        const int ptid = tid - 256;               // 0..63
        int pg = 0;

        for (int t = 0; t < SS; ++t) {
            if (ptid == 0 && layer > 0) poll_ge(&g_cnt[layer - 1], BPL * (t + 1));
            BAR2();
            for (int ch = 0; ch < nch; ++ch) {
                if (ch == ownStart) {
                    if (ptid == 0 && t > 0) poll_ge(&g_cnt[layer], BPL * t);
                    BAR2();
                }
                const int b = pg & 1;
                const int eph = (((pg >> 1) & 1) ^ 1);
                MBWAIT((b ? mbE1 : mbE0), eph);
                stageA64(smb, b, ch, layer, blk, ptid);
                stageB64(smb, b, ch, layer, t, Kin, ptid);
                CPARRIVE((b ? mbF1 : mbF0));
                ++pg;
            }
        }
    }

    // ---------------- phase 2: LayerNorm + output projection (consumers) ------
    if (tid < 256) {
        if (tid == 0) poll_ge(&g_cnt[3], BPL * SS);
        BAR1();

        float* As3 = smf;
        float* Ws3 = smf + 512 * PAD;
        float* red = smf + 512 * PAD + 64 * PAD;
        const int lane2 = tid & 31, wrp = tid >> 5;
        const int tc  = tid & 15, tr = tid >> 4;
        const int lkk = tid & 63, lr0 = tid >> 6;

        for (int i = 0; i < 4; ++i) {
            const int base_row = bx * 256 + i * 64;

            for (int rr = 0; rr < 64; ++rr) {
                const size_t row = (size_t)base_row + rr;
                const float v0 = __ldcg(&g_h3[row * HH + tid]);
                const float v1 = __ldcg(&g_h3[row * HH + tid + 256]);
                float s = v0 + v1, s2 = v0 * v0 + v1 * v1;
                #pragma unroll
                for (int off = 16; off > 0; off >>= 1) {
                    s  += __shfl_down_sync(0xffffffffu, s,  off);
                    s2 += __shfl_down_sync(0xffffffffu, s2, off);
                }
                if (lane2 == 0) { red[wrp] = s; red[8 + wrp] = s2; }
                BAR1();
                if (tid == 0) {
                    float S1 = 0.f, S2 = 0.f;
                    for (int jj = 0; jj < 8; ++jj) { S1 += red[jj]; S2 += red[8 + jj]; }
                    const float mu  = S1 * (1.0f / 512.0f);
                    const float var = S2 * (1.0f / 512.0f) - mu * mu;
                    red[16] = mu;
                    red[17] = rsqrtf(var + 1e-5f);
                }
                BAR1();
                const float mu = red[16], rstd = red[17];
                As3[tid * PAD + rr]         = (v0 - mu) * rstd * lng[tid]       + lnb[tid];
                As3[(tid + 256) * PAD + rr] = (v1 - mu) * rstd * lng[tid + 256] + lnb[tid + 256];
                BAR1();
            }

            float acc2[4][4];
            #pragma unroll
            for (int r = 0; r < 4; ++r)
                #pragma unroll
                for (int g = 0; g < 4; ++g) acc2[r][g] = 0.0f;

            for (int ch = 0; ch < 8; ++ch) {
                #pragma unroll
                for (int p = 0; p < 16; ++p) {
                    const int jc = p * 4 + lr0;
                    Ws3[lkk * PAD + (jc & 15) * 4 + (jc >> 4)] =
                        Wo[(size_t)jc * HH + ch * 64 + lkk];
                }
                BAR1();
                #pragma unroll 16
                for (int kk = 0; kk < 64; ++kk) {
                    const float4 a  = *(const float4*)(As3 + (ch * 64 + kk) * PAD + tr * 4);
                    const float4 wv = *(const float4*)(Ws3 + kk * PAD + tc * 4);
                    acc2[0][0] += a.x * wv.x; acc2[0][1] += a.x * wv.y;
                    acc2[0][2] += a.x * wv.z; acc2[0][3] += a.x * wv.w;
                    acc2[1][0] += a.y * wv.x; acc2[1][1] += a.y * wv.y;
                    acc2[1][2] += a.y * wv.z; acc2[1][3] += a.y * wv.w;
                    acc2[2][0] += a.z * wv.x; acc2[2][1] += a.z * wv.y;
                    acc2[2][2] += a.z * wv.z; acc2[2][3] += a.z * wv.w;
                    acc2[3][0] += a.w * wv.x; acc2[3][1] += a.w * wv.y;
                    acc2[3][2] += a.w * wv.z; acc2[3][3] += a.w * wv.w;
                }
                BAR1();
            }

            #pragma unroll
            for (int r = 0; r < 4; ++r) {
                const size_t row = (size_t)base_row + tr * 4 + r;
                #pragma unroll
                for (int g = 0; g < 4; ++g) {
                    const int d = g * 16 + tc;
                    out[row * DOUT + d] = acc2[r][g] + bo[d];
                }
            }
            BAR1();
        }
    }
}

extern "C" void kernel_launch(void* const* d_in, const int* in_sizes, int n_in,
                              void* d_out, int out_size) {
    const float* x   = (const float*)d_in[0];
    const float* W0  = (const float*)d_in[1];
    const float* b0  = (const float*)d_in[2];
    const float* W1  = (const float*)d_in[3];
    const float* b1  = (const float*)d_in[4];
    const float* W2  = (const float*)d_in[5];
    const float* b2  = (const float*)d_in[6];
    const float* W3  = (const float*)d_in[7];
    const float* b3  = (const float*)d_in[8];
    const float* lng = (const float*)d_in[9];
    const float* lnb = (const float*)d_in[10];
    const float* Wo  = (const float*)d_in[11];
    const float* bo  = (const float*)d_in[12];
    float* out = (float*)d_out;

    cudaFuncSetAttribute(lstm_mma_kernel,
                         cudaFuncAttributeMaxDynamicSharedMemorySize, SMEM_BYTES);
    lstm_mma_kernel<<<NB, NT, SMEM_BYTES>>>(
        x, W0, b0, W1, b1, W2, b2, W3, b3, lng, lnb, Wo, bo, out);
}